// round 14
// baseline (speedup 1.0000x reference)
#include <cuda_runtime.h>
#include <cuda_bf16.h>
#include <math.h>
#include <stdint.h>

// ---------------- problem constants ----------------
#define BB     16
#define HH     112
#define WWID   112
#define CC     96
#define NHEADS 3
#define HD     32
#define WS     7
#define NWIN   49
#define SHIFT  3
#define NW_IMG 256
#define M_TOK  200704
#define HID_D  384

typedef __nv_bfloat16 bf16;

#define W_QKV  0
#define W_PROJ 27648
#define W_FC1  36864
#define W_FC2  73728
#define W_TOT  110592

#define BM_ELEMS (256 * 3 * 49 * 56)
#define SSTR 104

// ---------------- scratch ----------------
__device__ bf16  g_qkv[(size_t)M_TOK * 3 * CC];
__device__ bf16  g_att[(size_t)M_TOK * CC];
__device__ float g_x1 [(size_t)M_TOK * CC];
__device__ bf16  g_y  [(size_t)M_TOK * CC];
__device__ bf16  g_h1 [(size_t)M_TOK * HID_D];
__device__ bf16  g_wb [W_TOT];
__device__ float g_bm [BM_ELEMS];

// ---------------- asm helpers ----------------
__device__ __forceinline__ void mma_bf16(float* c, uint32_t a0, uint32_t a1,
                                         uint32_t a2, uint32_t a3,
                                         uint32_t b0, uint32_t b1) {
    asm volatile(
        "mma.sync.aligned.m16n8k16.row.col.f32.bf16.bf16.f32 "
        "{%0,%1,%2,%3}, {%4,%5,%6,%7}, {%8,%9}, {%0,%1,%2,%3};"
        : "+f"(c[0]), "+f"(c[1]), "+f"(c[2]), "+f"(c[3])
        : "r"(a0), "r"(a1), "r"(a2), "r"(a3), "r"(b0), "r"(b1));
}

__device__ __forceinline__ void ldsm4(uint32_t& r0, uint32_t& r1,
                                      uint32_t& r2, uint32_t& r3, uint32_t addr) {
    asm volatile("ldmatrix.sync.aligned.m8n8.x4.shared.b16 {%0,%1,%2,%3}, [%4];"
                 : "=r"(r0), "=r"(r1), "=r"(r2), "=r"(r3) : "r"(addr));
}

__device__ __forceinline__ void cp16(uint32_t saddr, const void* g) {
    asm volatile("cp.async.cg.shared.global [%0], [%1], 16;" :: "r"(saddr), "l"(g));
}
__device__ __forceinline__ void cp_commit() { asm volatile("cp.async.commit_group;"); }
__device__ __forceinline__ void cp_wait0()  { asm volatile("cp.async.wait_group 0;"); }
__device__ __forceinline__ void cp_wait1()  { asm volatile("cp.async.wait_group 1;"); }

__device__ __forceinline__ uint32_t pack_bf16x2(float lo, float hi) {
    uint32_t r;
    asm("cvt.rn.bf16x2.f32 %0, %1, %2;" : "=r"(r) : "f"(hi), "f"(lo));
    return r;
}

// scatter: window-layout row m -> (B,L,C) base index (reverse shift)
__device__ __forceinline__ size_t scatter_base(int m) {
    int win = m / NWIN, nn = m % NWIN;
    int b  = win >> 8;
    int wi = win & 255;
    int wh = wi >> 4, ww = wi & 15;
    int ii = nn / WS, jj = nn % WS;
    int r = wh * WS + ii + SHIFT; if (r >= HH)   r -= HH;
    int c = ww * WS + jj + SHIFT; if (c >= WWID) c -= WWID;
    return ((size_t)b * (HH * WWID) + r * WWID + c) * CC;
}

// ---------------- setup kernels ----------------
__global__ void convert_w(const float* __restrict__ qkv_w, const float* __restrict__ proj_w,
                          const float* __restrict__ fc1_w, const float* __restrict__ fc2_w,
                          bf16* __restrict__ wb)
{
    int i = blockIdx.x * 256 + threadIdx.x;
    if (i >= W_TOT) return;
    float v;
    if      (i < W_PROJ) v = qkv_w[i - W_QKV];
    else if (i < W_FC1)  v = proj_w[i - W_PROJ];
    else if (i < W_FC2)  v = fc1_w[i - W_FC1];
    else                 v = fc2_w[i - W_FC2];
    wb[i] = __float2bfloat16(v);
}

__global__ void build_bm(const float* __restrict__ relb, const float* __restrict__ mask,
                         float* __restrict__ bm)
{
    int idx = blockIdx.x * 256 + threadIdx.x;
    if (idx >= BM_ELEMS) return;
    int c   = idx % 56;
    int tmp = idx / 56;
    int r   = tmp % 49;  tmp /= 49;
    int h   = tmp % 3;
    int wi  = tmp / 3;
    float v;
    if (c < 49) {
        int i1 = r / WS, j1 = r % WS, i2 = c / WS, j2 = c % WS;
        int ridx = (i1 - i2 + WS - 1) * (2 * WS - 1) + (j1 - j2 + WS - 1);
        v = relb[ridx * NHEADS + h] + mask[(size_t)wi * (NWIN * NWIN) + r * NWIN + c];
    } else {
        v = -1e9f;
    }
    bm[idx] = v;
}

// ---------------- bf16 TC GEMM, K = KTILES*96 -------------------------------
// BM=128, BN=96, 384 threads (12 warps: 4m x 3n), warp tile 32x32.
// EPI 0: bias -> bf16 | 1: bias+GELU -> bf16
// EPI 2: bias + scatter + residual -> f32 x1, then FUSED LN2 -> y (bf16)
// EPI 3: bias + residual -> f32
// LN1 != 0 (KTILES must be 1): A comes from fp32 `res` via shift-gather + LN
//   (ln gain/bias passed in n2g/n2b).
template<int KTILES, int EPI, int LN1, typename OUTT>
__global__ __launch_bounds__(384)
void gemm_tc(const bf16* __restrict__ A, const bf16* __restrict__ W,
             const float* __restrict__ bias, OUTT* __restrict__ out,
             const float* __restrict__ res, int N,
             const float* __restrict__ n2g, const float* __restrict__ n2b,
             bf16* __restrict__ yout)
{
    constexpr int K    = KTILES * 96;
    constexpr int NBUF = (KTILES > 1) ? 2 : 1;
    constexpr int ABUF = 128 * SSTR;

    extern __shared__ bf16 smem[];
    bf16*  As = smem;
    bf16*  Ws = smem + NBUF * ABUF;
    float* sx = (float*)smem;            // EPI==2 LN scratch (aliases staging)

    int tid  = threadIdx.x;
    int wid  = tid >> 5, lane = tid & 31;
    int g    = lane >> 2, t = lane & 3;
    int wm   = wid & 3, wn = wid >> 2;
    int m0   = blockIdx.x * 128, n0 = blockIdx.y * 96;

    uint32_t as_base = (uint32_t)__cvta_generic_to_shared(As);
    uint32_t ws_base = (uint32_t)__cvta_generic_to_shared(Ws);

    int lrow = lane & 7, lsel = lane >> 3;
    int ra = (lsel & 1) * 8 + lrow;
    int caoff = (lsel >> 1) * 8;

    float c[2][4][4];
    #pragma unroll
    for (int i = 0; i < 2; i++)
        #pragma unroll
        for (int j = 0; j < 4; j++)
            #pragma unroll
            for (int l = 0; l < 4; l++) c[i][j][l] = 0.f;

    auto stageW = [&](int buf, int kt) {
        #pragma unroll
        for (int i = 0; i < 3; i++) {
            int idx = tid + i * 384;
            int row = idx / 12, ch = idx % 12;
            cp16(ws_base + ((buf * 96 + row) * SSTR + ch * 8) * 2,
                 W + (size_t)(n0 + row) * K + kt * 96 + ch * 8);
        }
    };
    auto stageA = [&](int buf, int kt) {
        #pragma unroll
        for (int i = 0; i < 4; i++) {
            int idx = tid + i * 384;
            int row = idx / 12, ch = idx % 12;
            cp16(as_base + ((buf * 128 + row) * SSTR + ch * 8) * 2,
                 A + (size_t)(m0 + row) * K + kt * 96 + ch * 8);
        }
    };

    if (LN1) {
        // W staging overlaps the LN computation
        stageW(0, 0);
        cp_commit();
        for (int tok = wid; tok < 128; tok += 12) {
            const float* src = res + scatter_base(m0 + tok);
            float v0 = src[lane], v1 = src[lane + 32], v2 = src[lane + 64];
            float s = v0 + v1 + v2;
            #pragma unroll
            for (int o = 16; o; o >>= 1) s += __shfl_xor_sync(0xffffffffu, s, o);
            float mean = s * (1.0f / 96.0f);
            float d0 = v0 - mean, d1 = v1 - mean, d2 = v2 - mean;
            float q = d0 * d0 + d1 * d1 + d2 * d2;
            #pragma unroll
            for (int o = 16; o; o >>= 1) q += __shfl_xor_sync(0xffffffffu, q, o);
            float rstd = rsqrtf(q * (1.0f / 96.0f) + 1e-5f);
            As[tok * SSTR + lane]      = __float2bfloat16(d0 * rstd * n2g[lane]      + n2b[lane]);
            As[tok * SSTR + lane + 32] = __float2bfloat16(d1 * rstd * n2g[lane + 32] + n2b[lane + 32]);
            As[tok * SSTR + lane + 64] = __float2bfloat16(d2 * rstd * n2g[lane + 64] + n2b[lane + 64]);
        }
        cp_wait0();
    } else {
        stageA(0, 0);
        stageW(0, 0);
        cp_commit();
    }

    #pragma unroll
    for (int kt = 0; kt < KTILES; kt++) {
        int buf = kt & 1;
        if (KTILES > 1 && kt + 1 < KTILES) {
            stageA((kt + 1) & 1, kt + 1);
            stageW((kt + 1) & 1, kt + 1);
            cp_commit();
            cp_wait1();
        } else if (!LN1) {
            cp_wait0();
        }
        __syncthreads();

        #pragma unroll
        for (int kk = 0; kk < 6; kk++) {
            int kc = kk * 16 + caoff;
            uint32_t a[2][4];
            #pragma unroll
            for (int mt = 0; mt < 2; mt++) {
                int row = wm * 32 + mt * 16 + ra;
                ldsm4(a[mt][0], a[mt][1], a[mt][2], a[mt][3],
                      as_base + ((buf * 128 + row) * SSTR + kc) * 2);
            }
            uint32_t b[2][4];
            #pragma unroll
            for (int np = 0; np < 2; np++) {
                int row = wn * 32 + np * 16 + ra;
                ldsm4(b[np][0], b[np][1], b[np][2], b[np][3],
                      ws_base + ((buf * 96 + row) * SSTR + kc) * 2);
            }
            #pragma unroll
            for (int nt = 0; nt < 4; nt++) {
                uint32_t b0 = b[nt >> 1][nt & 1];
                uint32_t b1 = b[nt >> 1][(nt & 1) + 2];
                #pragma unroll
                for (int mt = 0; mt < 2; mt++)
                    mma_bf16(c[mt][nt], a[mt][0], a[mt][1], a[mt][2], a[mt][3], b0, b1);
            }
        }
        if (KTILES > 1 && kt + 1 < KTILES) __syncthreads();
    }

    if (EPI == 2) __syncthreads();   // staging smem dead; alias as LN scratch

    #pragma unroll
    for (int mt = 0; mt < 2; mt++) {
        #pragma unroll
        for (int rh = 0; rh < 2; rh++) {
            int m = m0 + wm * 32 + mt * 16 + g + rh * 8;
            size_t rowbase;
            if (EPI == 2) rowbase = scatter_base(m);
            else          rowbase = (size_t)m * N;
            #pragma unroll
            for (int nt = 0; nt < 4; nt++) {
                #pragma unroll
                for (int j = 0; j < 2; j++) {
                    int n = n0 + wn * 32 + nt * 8 + 2 * t + j;
                    float v = c[mt][nt][rh * 2 + j] + bias[n];
                    if (EPI == 0) {
                        out[rowbase + n] = (OUTT)__float2bfloat16(v);
                    } else if (EPI == 1) {
                        float gl = 0.5f * v * (1.0f + erff(v * 0.70710678118654752f));
                        out[rowbase + n] = (OUTT)__float2bfloat16(gl);
                    } else if (EPI == 2) {
                        float xv = res[rowbase + n] + v;
                        out[rowbase + n] = (OUTT)xv;
                        sx[(m - m0) * 96 + n] = xv;
                    } else {
                        out[rowbase + n] = (OUTT)(res[rowbase + n] + v);
                    }
                }
            }
        }
    }

    // ---- fused LN2 (EPI==2 only) ----
    if (EPI == 2) {
        __syncthreads();
        for (int tok = wid; tok < 128; tok += 12) {
            float v0 = sx[tok * 96 + lane];
            float v1 = sx[tok * 96 + lane + 32];
            float v2 = sx[tok * 96 + lane + 64];
            float s = v0 + v1 + v2;
            #pragma unroll
            for (int o = 16; o; o >>= 1) s += __shfl_xor_sync(0xffffffffu, s, o);
            float mean = s * (1.0f / 96.0f);
            float d0 = v0 - mean, d1 = v1 - mean, d2 = v2 - mean;
            float q = d0 * d0 + d1 * d1 + d2 * d2;
            #pragma unroll
            for (int o = 16; o; o >>= 1) q += __shfl_xor_sync(0xffffffffu, q, o);
            float rstd = rsqrtf(q * (1.0f / 96.0f) + 1e-5f);
            size_t rb = scatter_base(m0 + tok);
            yout[rb + lane]      = __float2bfloat16(d0 * rstd * n2g[lane]      + n2b[lane]);
            yout[rb + lane + 32] = __float2bfloat16(d1 * rstd * n2g[lane + 32] + n2b[lane + 32]);
            yout[rb + lane + 64] = __float2bfloat16(d2 * rstd * n2g[lane + 64] + n2b[lane + 64]);
        }
    }
}

// ---------------- attention: 3 heads in parallel, register softmax ----------
__global__ __launch_bounds__(384)
void attn_tc(const bf16* __restrict__ qkv, const float* __restrict__ bm,
             bf16* __restrict__ out)
{
    __shared__ bf16 qs [NHEADS][64][40];
    __shared__ bf16 ks_[NHEADS][56][40];
    __shared__ bf16 vt [NHEADS][32][72];

    int win  = blockIdx.x;
    int tid  = threadIdx.x;
    int wid  = tid >> 5, lane = tid & 31;
    int g    = lane >> 2, t = lane & 3;
    int h    = wid >> 2, wq = wid & 3;
    const float scale = 0.17677669529663689f;

    const bf16* base = qkv + (size_t)win * NWIN * (3 * CC);
    int r0 = wq * 16 + g, r1 = r0 + 8;
    bool v0ok = r0 < NWIN, v1ok = r1 < NWIN;

    // ---- stage Q / K / V^T for all heads ----
    for (int p = tid; p < NHEADS * 2048; p += 384) {
        int hh = p >> 11, rem = p & 2047;
        int n = rem >> 5, d = rem & 31;
        qs[hh][n][d] = (n < NWIN) ? base[(size_t)n * (3 * CC) + hh * HD + d] : (bf16)0.f;
    }
    for (int p = tid; p < NHEADS * 2048; p += 384) {
        int hh = p >> 11, rem = p & 2047;
        int n = rem >> 5, d = rem & 31;
        bf16 kv = (n < NWIN) ? base[(size_t)n * (3 * CC) + CC + hh * HD + d] : (bf16)0.f;
        bf16 vv = (n < NWIN) ? base[(size_t)n * (3 * CC) + 2 * CC + hh * HD + d] : (bf16)0.f;
        if (n < 56) ks_[hh][n][d] = kv;
        vt[hh][d][n] = vv;
    }
    __syncthreads();

    // ---- S = Q K^T ----
    float sc[7][4];
    #pragma unroll
    for (int nt = 0; nt < 7; nt++)
        #pragma unroll
        for (int l = 0; l < 4; l++) sc[nt][l] = 0.f;

    #pragma unroll
    for (int ks = 0; ks < 2; ks++) {
        int kc = ks * 16 + 2 * t;
        uint32_t a0 = *(const uint32_t*)&qs[h][r0][kc];
        uint32_t a1 = *(const uint32_t*)&qs[h][r1][kc];
        uint32_t a2 = *(const uint32_t*)&qs[h][r0][kc + 8];
        uint32_t a3 = *(const uint32_t*)&qs[h][r1][kc + 8];
        #pragma unroll
        for (int nt = 0; nt < 7; nt++) {
            int nr = nt * 8 + g;
            uint32_t b0 = *(const uint32_t*)&ks_[h][nr][kc];
            uint32_t b1 = *(const uint32_t*)&ks_[h][nr][kc + 8];
            mma_bf16(sc[nt], a0, a1, a2, a3, b0, b1);
        }
    }

    const float* bmh = bm + ((size_t)((win & 255) * 3 + h)) * (49 * 56);
    #pragma unroll
    for (int nt = 0; nt < 7; nt++) {
        int cbase = nt * 8 + 2 * t;
        #pragma unroll
        for (int j = 0; j < 2; j++) {
            sc[nt][j]     = v0ok ? sc[nt][j]     * scale + bmh[r0 * 56 + cbase + j] : 0.f;
            sc[nt][2 + j] = v1ok ? sc[nt][2 + j] * scale + bmh[r1 * 56 + cbase + j] : 0.f;
        }
    }

    // ---- register softmax (quad reduction) ----
    float mx0 = -1e30f, mx1 = -1e30f;
    #pragma unroll
    for (int nt = 0; nt < 7; nt++) {
        mx0 = fmaxf(mx0, fmaxf(sc[nt][0], sc[nt][1]));
        mx1 = fmaxf(mx1, fmaxf(sc[nt][2], sc[nt][3]));
    }
    #pragma unroll
    for (int o = 1; o <= 2; o <<= 1) {
        mx0 = fmaxf(mx0, __shfl_xor_sync(0xffffffffu, mx0, o));
        mx1 = fmaxf(mx1, __shfl_xor_sync(0xffffffffu, mx1, o));
    }
    float sum0 = 0.f, sum1 = 0.f;
    #pragma unroll
    for (int nt = 0; nt < 7; nt++) {
        sc[nt][0] = __expf(sc[nt][0] - mx0); sum0 += sc[nt][0];
        sc[nt][1] = __expf(sc[nt][1] - mx0); sum0 += sc[nt][1];
        sc[nt][2] = __expf(sc[nt][2] - mx1); sum1 += sc[nt][2];
        sc[nt][3] = __expf(sc[nt][3] - mx1); sum1 += sc[nt][3];
    }
    #pragma unroll
    for (int o = 1; o <= 2; o <<= 1) {
        sum0 += __shfl_xor_sync(0xffffffffu, sum0, o);
        sum1 += __shfl_xor_sync(0xffffffffu, sum1, o);
    }
    float inv0 = 1.0f / sum0, inv1 = 1.0f / sum1;
    #pragma unroll
    for (int nt = 0; nt < 7; nt++) {
        sc[nt][0] *= inv0; sc[nt][1] *= inv0;
        sc[nt][2] *= inv1; sc[nt][3] *= inv1;
    }

    // ---- O = P V ----
    float oc[4][4];
    #pragma unroll
    for (int nt = 0; nt < 4; nt++)
        #pragma unroll
        for (int l = 0; l < 4; l++) oc[nt][l] = 0.f;

    #pragma unroll
    for (int ks = 0; ks < 4; ks++) {
        uint32_t a0 = pack_bf16x2(sc[2 * ks][0], sc[2 * ks][1]);
        uint32_t a1 = pack_bf16x2(sc[2 * ks][2], sc[2 * ks][3]);
        uint32_t a2 = 0, a3 = 0;
        if (ks < 3) {
            a2 = pack_bf16x2(sc[2 * ks + 1][0], sc[2 * ks + 1][1]);
            a3 = pack_bf16x2(sc[2 * ks + 1][2], sc[2 * ks + 1][3]);
        }
        int kc = ks * 16 + 2 * t;
        #pragma unroll
        for (int nt = 0; nt < 4; nt++) {
            int nr = nt * 8 + g;
            uint32_t b0 = *(const uint32_t*)&vt[h][nr][kc];
            uint32_t b1 = *(const uint32_t*)&vt[h][nr][kc + 8];
            mma_bf16(oc[nt], a0, a1, a2, a3, b0, b1);
        }
    }

    #pragma unroll
    for (int nt = 0; nt < 4; nt++) {
        #pragma unroll
        for (int j = 0; j < 2; j++) {
            int d = nt * 8 + 2 * t + j;
            if (v0ok)
                out[((size_t)win * NWIN + r0) * CC + h * HD + d] =
                    __float2bfloat16(oc[nt][j]);
            if (v1ok)
                out[((size_t)win * NWIN + r1) * CC + h * HD + d] =
                    __float2bfloat16(oc[nt][2 + j]);
        }
    }
}

// ---------------- launch ----------------
extern "C" void kernel_launch(void* const* d_in, const int* in_sizes, int n_in,
                              void* d_out, int out_size)
{
    const float* x      = (const float*)d_in[0];
    const float* mask   = (const float*)d_in[1];
    const float* n1g    = (const float*)d_in[2];
    const float* n1b    = (const float*)d_in[3];
    const float* qkv_w  = (const float*)d_in[4];
    const float* qkv_b  = (const float*)d_in[5];
    const float* relb   = (const float*)d_in[6];
    const float* proj_w = (const float*)d_in[7];
    const float* proj_b = (const float*)d_in[8];
    const float* n2g    = (const float*)d_in[9];
    const float* n2b    = (const float*)d_in[10];
    const float* fc1_w  = (const float*)d_in[11];
    const float* fc1_b  = (const float*)d_in[12];
    const float* fc2_w  = (const float*)d_in[13];
    const float* fc2_b  = (const float*)d_in[14];
    float* out = (float*)d_out;

    bf16 *qkvb, *att, *y, *h1, *wb;
    float *x1, *bm;
    cudaGetSymbolAddress((void**)&qkvb, g_qkv);
    cudaGetSymbolAddress((void**)&att,  g_att);
    cudaGetSymbolAddress((void**)&x1,   g_x1);
    cudaGetSymbolAddress((void**)&y,    g_y);
    cudaGetSymbolAddress((void**)&h1,   g_h1);
    cudaGetSymbolAddress((void**)&wb,   g_wb);
    cudaGetSymbolAddress((void**)&bm,   g_bm);

    const int GM = M_TOK / 128;         // 1568

    const int SM1    = (128 + 96) * SSTR * 2;       // 46592 B  (KTILES=1)
    const int SMPROJ = 128 * 96 * 4;                // 49152 B  (LN scratch)
    const int SM4    = 2 * (128 + 96) * SSTR * 2;   // 93184 B  (KTILES=4)

    cudaFuncSetAttribute((const void*)gemm_tc<1, 0, 1, bf16>,
                         cudaFuncAttributeMaxDynamicSharedMemorySize, SM1);
    cudaFuncSetAttribute((const void*)gemm_tc<1, 2, 0, float>,
                         cudaFuncAttributeMaxDynamicSharedMemorySize, SMPROJ);
    cudaFuncSetAttribute((const void*)gemm_tc<1, 1, 0, bf16>,
                         cudaFuncAttributeMaxDynamicSharedMemorySize, SM1);
    cudaFuncSetAttribute((const void*)gemm_tc<4, 3, 0, float>,
                         cudaFuncAttributeMaxDynamicSharedMemorySize, SM4);

    convert_w<<<(W_TOT + 255) / 256, 256>>>(qkv_w, proj_w, fc1_w, fc2_w, wb);
    build_bm<<<(BM_ELEMS + 255) / 256, 256>>>(relb, mask, bm);
    // qkv with FUSED LN1 (reads x directly with shift-gather)
    gemm_tc<1, 0, 1, bf16><<<dim3(GM, 3), 384, SM1>>>(nullptr, wb + W_QKV, qkv_b, qkvb,
                                                      x, 3 * CC, n1g, n1b, nullptr);
    attn_tc<<<BB * NW_IMG, 384>>>(qkvb, bm, att);
    // proj + residual scatter + FUSED LN2 -> y
    gemm_tc<1, 2, 0, float><<<dim3(GM, 1), 384, SMPROJ>>>(att, wb + W_PROJ, proj_b, x1,
                                                          x, CC, n2g, n2b, y);
    gemm_tc<1, 1, 0, bf16><<<dim3(GM, 4), 384, SM1>>>(y, wb + W_FC1, fc1_b, h1,
                                                      nullptr, HID_D, nullptr, nullptr, nullptr);
    gemm_tc<4, 3, 0, float><<<dim3(GM, 1), 384, SM4>>>(h1, wb + W_FC2, fc2_b, out,
                                                       x1, CC, nullptr, nullptr, nullptr);
}

// round 15
// speedup vs baseline: 1.7123x; 1.7123x over previous
#include <cuda_runtime.h>
#include <cuda_bf16.h>
#include <math.h>
#include <stdint.h>

// ---------------- problem constants ----------------
#define BB     16
#define HH     112
#define WWID   112
#define CC     96
#define NHEADS 3
#define HD     32
#define WS     7
#define NWIN   49
#define SHIFT  3
#define NW_IMG 256
#define M_TOK  200704
#define HID_D  384

typedef __nv_bfloat16 bf16;

#define W_QKV  0
#define W_PROJ 27648
#define W_FC1  36864
#define W_FC2  73728
#define W_TOT  110592

#define BM_ELEMS (256 * 3 * 49 * 56)
#define SSTR 104

// ---------------- scratch ----------------
__device__ bf16  g_xw [(size_t)M_TOK * CC];
__device__ bf16  g_qkv[(size_t)M_TOK * 3 * CC];
__device__ bf16  g_att[(size_t)M_TOK * CC];
__device__ float g_x1 [(size_t)M_TOK * CC];
__device__ bf16  g_y  [(size_t)M_TOK * CC];
__device__ bf16  g_h1 [(size_t)M_TOK * HID_D];
__device__ bf16  g_wb [W_TOT];
__device__ float g_bm [BM_ELEMS];

// ---------------- asm helpers ----------------
__device__ __forceinline__ void mma_bf16(float* c, uint32_t a0, uint32_t a1,
                                         uint32_t a2, uint32_t a3,
                                         uint32_t b0, uint32_t b1) {
    asm volatile(
        "mma.sync.aligned.m16n8k16.row.col.f32.bf16.bf16.f32 "
        "{%0,%1,%2,%3}, {%4,%5,%6,%7}, {%8,%9}, {%0,%1,%2,%3};"
        : "+f"(c[0]), "+f"(c[1]), "+f"(c[2]), "+f"(c[3])
        : "r"(a0), "r"(a1), "r"(a2), "r"(a3), "r"(b0), "r"(b1));
}

__device__ __forceinline__ void ldsm4(uint32_t& r0, uint32_t& r1,
                                      uint32_t& r2, uint32_t& r3, uint32_t addr) {
    asm volatile("ldmatrix.sync.aligned.m8n8.x4.shared.b16 {%0,%1,%2,%3}, [%4];"
                 : "=r"(r0), "=r"(r1), "=r"(r2), "=r"(r3) : "r"(addr));
}

__device__ __forceinline__ void cp16(uint32_t saddr, const void* g) {
    asm volatile("cp.async.ca.shared.global [%0], [%1], 16;" :: "r"(saddr), "l"(g));
}
__device__ __forceinline__ void cp_commit() { asm volatile("cp.async.commit_group;"); }
__device__ __forceinline__ void cp_wait0()  { asm volatile("cp.async.wait_group 0;"); }
__device__ __forceinline__ void cp_wait1()  { asm volatile("cp.async.wait_group 1;"); }

__device__ __forceinline__ uint32_t pack_bf16x2(float lo, float hi) {
    uint32_t r;
    asm("cvt.rn.bf16x2.f32 %0, %1, %2;" : "=r"(r) : "f"(hi), "f"(lo));
    return r;
}

// scatter: window-layout row m -> (B,L,C) base index (reverse shift)
__device__ __forceinline__ size_t scatter_base(int m) {
    int win = m / NWIN, nn = m % NWIN;
    int b  = win >> 8;
    int wi = win & 255;
    int wh = wi >> 4, ww = wi & 15;
    int ii = nn / WS, jj = nn % WS;
    int r = wh * WS + ii + SHIFT; if (r >= HH)   r -= HH;
    int c = ww * WS + jj + SHIFT; if (c >= WWID) c -= WWID;
    return ((size_t)b * (HH * WWID) + r * WWID + c) * CC;
}

// ---------------- setup kernels ----------------
__global__ void convert_w(const float* __restrict__ qkv_w, const float* __restrict__ proj_w,
                          const float* __restrict__ fc1_w, const float* __restrict__ fc2_w,
                          bf16* __restrict__ wb)
{
    int i = blockIdx.x * 256 + threadIdx.x;
    if (i >= W_TOT) return;
    float v;
    if      (i < W_PROJ) v = qkv_w[i - W_QKV];
    else if (i < W_FC1)  v = proj_w[i - W_PROJ];
    else if (i < W_FC2)  v = fc1_w[i - W_FC1];
    else                 v = fc2_w[i - W_FC2];
    wb[i] = __float2bfloat16(v);
}

__global__ void build_bm(const float* __restrict__ relb, const float* __restrict__ mask,
                         float* __restrict__ bm)
{
    int idx = blockIdx.x * 256 + threadIdx.x;
    if (idx >= BM_ELEMS) return;
    int c   = idx % 56;
    int tmp = idx / 56;
    int r   = tmp % 49;  tmp /= 49;
    int h   = tmp % 3;
    int wi  = tmp / 3;
    float v;
    if (c < 49) {
        int i1 = r / WS, j1 = r % WS, i2 = c / WS, j2 = c % WS;
        int ridx = (i1 - i2 + WS - 1) * (2 * WS - 1) + (j1 - j2 + WS - 1);
        v = relb[ridx * NHEADS + h] + mask[(size_t)wi * (NWIN * NWIN) + r * NWIN + c];
    } else {
        v = -1e9f;
    }
    bm[idx] = v;
}

// ---------------- LN1 (warp per token), gather + bf16 output ----------------
__global__ __launch_bounds__(256)
void ln_kernel(const float* __restrict__ x, const float* __restrict__ g,
               const float* __restrict__ beta, bf16* __restrict__ out)
{
    int t    = (blockIdx.x * blockDim.x + threadIdx.x) >> 5;
    int lane = threadIdx.x & 31;
    if (t >= M_TOK) return;

    int win = t / NWIN, n = t % NWIN;
    int b  = win >> 8;
    int wi = win & 255;
    int wh = wi >> 4, ww = wi & 15;
    int i = n / WS, j = n % WS;
    int r = wh * WS + i + SHIFT; if (r >= HH)   r -= HH;
    int c = ww * WS + j + SHIFT; if (c >= WWID) c -= WWID;
    const float* src = x + ((size_t)b * (HH * WWID) + r * WWID + c) * CC;

    float v0 = src[lane], v1 = src[lane + 32], v2 = src[lane + 64];
    float s = v0 + v1 + v2;
    #pragma unroll
    for (int o = 16; o; o >>= 1) s += __shfl_xor_sync(0xffffffffu, s, o);
    float mean = s * (1.0f / 96.0f);
    float d0 = v0 - mean, d1 = v1 - mean, d2 = v2 - mean;
    float q = d0 * d0 + d1 * d1 + d2 * d2;
    #pragma unroll
    for (int o = 16; o; o >>= 1) q += __shfl_xor_sync(0xffffffffu, q, o);
    float rstd = rsqrtf(q * (1.0f / 96.0f) + 1e-5f);

    bf16* dst = out + (size_t)t * CC;
    dst[lane]      = __float2bfloat16(d0 * rstd * g[lane]      + beta[lane]);
    dst[lane + 32] = __float2bfloat16(d1 * rstd * g[lane + 32] + beta[lane + 32]);
    dst[lane + 64] = __float2bfloat16(d2 * rstd * g[lane + 64] + beta[lane + 64]);
}

// ---------------- bf16 TC GEMM, K = KTILES*96 -------------------------------
// BM=128, BN=96, 384 threads (12 warps: 4m x 3n), warp tile 32x32.
// EPI 0: bias -> bf16 (packed 4B stores) | 1: bias+GELU -> bf16 (packed)
// EPI 2: bias + scatter + residual -> f32 x1 (float2), then FUSED LN2 -> y
// EPI 3: bias + residual -> f32 (float2)
template<int KTILES, int EPI, typename OUTT>
__global__ __launch_bounds__(384)
void gemm_tc(const bf16* __restrict__ A, const bf16* __restrict__ W,
             const float* __restrict__ bias, OUTT* __restrict__ out,
             const float* __restrict__ res, int N,
             const float* __restrict__ n2g, const float* __restrict__ n2b,
             bf16* __restrict__ yout)
{
    constexpr int K    = KTILES * 96;
    constexpr int NBUF = (KTILES > 1) ? 2 : 1;
    constexpr int ABUF = 128 * SSTR;

    extern __shared__ bf16 smem[];
    bf16*  As = smem;
    bf16*  Ws = smem + NBUF * ABUF;
    float* sx = (float*)smem;            // EPI==2 LN scratch (aliases staging)

    int tid  = threadIdx.x;
    int wid  = tid >> 5, lane = tid & 31;
    int g    = lane >> 2, t = lane & 3;
    int wm   = wid & 3, wn = wid >> 2;
    int m0   = blockIdx.x * 128, n0 = blockIdx.y * 96;

    uint32_t as_base = (uint32_t)__cvta_generic_to_shared(As);
    uint32_t ws_base = (uint32_t)__cvta_generic_to_shared(Ws);

    int lrow = lane & 7, lsel = lane >> 3;
    int ra = (lsel & 1) * 8 + lrow;
    int caoff = (lsel >> 1) * 8;

    float c[2][4][4];
    #pragma unroll
    for (int i = 0; i < 2; i++)
        #pragma unroll
        for (int j = 0; j < 4; j++)
            #pragma unroll
            for (int l = 0; l < 4; l++) c[i][j][l] = 0.f;

    auto stage = [&](int buf, int kt) {
        #pragma unroll
        for (int i = 0; i < 4; i++) {
            int idx = tid + i * 384;
            int row = idx / 12, ch = idx % 12;
            cp16(as_base + ((buf * 128 + row) * SSTR + ch * 8) * 2,
                 A + (size_t)(m0 + row) * K + kt * 96 + ch * 8);
        }
        #pragma unroll
        for (int i = 0; i < 3; i++) {
            int idx = tid + i * 384;
            int row = idx / 12, ch = idx % 12;
            cp16(ws_base + ((buf * 96 + row) * SSTR + ch * 8) * 2,
                 W + (size_t)(n0 + row) * K + kt * 96 + ch * 8);
        }
    };

    stage(0, 0);
    cp_commit();

    #pragma unroll
    for (int kt = 0; kt < KTILES; kt++) {
        int buf = kt & 1;
        if (KTILES > 1 && kt + 1 < KTILES) {
            stage((kt + 1) & 1, kt + 1);
            cp_commit();
            cp_wait1();
        } else {
            cp_wait0();
        }
        __syncthreads();

        #pragma unroll
        for (int kk = 0; kk < 6; kk++) {
            int kc = kk * 16 + caoff;
            uint32_t a[2][4];
            #pragma unroll
            for (int mt = 0; mt < 2; mt++) {
                int row = wm * 32 + mt * 16 + ra;
                ldsm4(a[mt][0], a[mt][1], a[mt][2], a[mt][3],
                      as_base + ((buf * 128 + row) * SSTR + kc) * 2);
            }
            uint32_t b[2][4];
            #pragma unroll
            for (int np = 0; np < 2; np++) {
                int row = wn * 32 + np * 16 + ra;
                ldsm4(b[np][0], b[np][1], b[np][2], b[np][3],
                      ws_base + ((buf * 96 + row) * SSTR + kc) * 2);
            }
            #pragma unroll
            for (int nt = 0; nt < 4; nt++) {
                uint32_t b0 = b[nt >> 1][nt & 1];
                uint32_t b1 = b[nt >> 1][(nt & 1) + 2];
                #pragma unroll
                for (int mt = 0; mt < 2; mt++)
                    mma_bf16(c[mt][nt], a[mt][0], a[mt][1], a[mt][2], a[mt][3], b0, b1);
            }
        }
        if (KTILES > 1 && kt + 1 < KTILES) __syncthreads();
    }

    if (EPI == 2) __syncthreads();   // staging smem dead; alias as LN scratch

    #pragma unroll
    for (int mt = 0; mt < 2; mt++) {
        #pragma unroll
        for (int rh = 0; rh < 2; rh++) {
            int m = m0 + wm * 32 + mt * 16 + g + rh * 8;
            size_t rowbase;
            if (EPI == 2) rowbase = scatter_base(m);
            else          rowbase = (size_t)m * N;
            #pragma unroll
            for (int nt = 0; nt < 4; nt++) {
                int n = n0 + wn * 32 + nt * 8 + 2 * t;      // even column index
                float v0 = c[mt][nt][rh * 2 + 0] + bias[n];
                float v1 = c[mt][nt][rh * 2 + 1] + bias[n + 1];
                if (EPI == 0) {
                    *(uint32_t*)((bf16*)out + rowbase + n) = pack_bf16x2(v0, v1);
                } else if (EPI == 1) {
                    float g0 = 0.5f * v0 * (1.0f + erff(v0 * 0.70710678118654752f));
                    float g1 = 0.5f * v1 * (1.0f + erff(v1 * 0.70710678118654752f));
                    *(uint32_t*)((bf16*)out + rowbase + n) = pack_bf16x2(g0, g1);
                } else if (EPI == 2) {
                    float2 rv = *(const float2*)(res + rowbase + n);
                    float x0 = rv.x + v0, x1v = rv.y + v1;
                    float2 ov; ov.x = x0; ov.y = x1v;
                    *(float2*)((float*)out + rowbase + n) = ov;
                    sx[(m - m0) * 96 + n]     = x0;
                    sx[(m - m0) * 96 + n + 1] = x1v;
                } else {
                    float2 rv = *(const float2*)(res + rowbase + n);
                    float2 ov; ov.x = rv.x + v0; ov.y = rv.y + v1;
                    *(float2*)((float*)out + rowbase + n) = ov;
                }
            }
        }
    }

    // ---- fused LN2 (EPI==2 only) ----
    if (EPI == 2) {
        __syncthreads();
        for (int tok = wid; tok < 128; tok += 12) {
            float v0 = sx[tok * 96 + lane];
            float v1 = sx[tok * 96 + lane + 32];
            float v2 = sx[tok * 96 + lane + 64];
            float s = v0 + v1 + v2;
            #pragma unroll
            for (int o = 16; o; o >>= 1) s += __shfl_xor_sync(0xffffffffu, s, o);
            float mean = s * (1.0f / 96.0f);
            float d0 = v0 - mean, d1 = v1 - mean, d2 = v2 - mean;
            float q = d0 * d0 + d1 * d1 + d2 * d2;
            #pragma unroll
            for (int o = 16; o; o >>= 1) q += __shfl_xor_sync(0xffffffffu, q, o);
            float rstd = rsqrtf(q * (1.0f / 96.0f) + 1e-5f);
            size_t rb = scatter_base(m0 + tok);
            yout[rb + lane]      = __float2bfloat16(d0 * rstd * n2g[lane]      + n2b[lane]);
            yout[rb + lane + 32] = __float2bfloat16(d1 * rstd * n2g[lane + 32] + n2b[lane + 32]);
            yout[rb + lane + 64] = __float2bfloat16(d2 * rstd * n2g[lane + 64] + n2b[lane + 64]);
        }
    }
}

// ---------------- attention: register softmax, P-in-register PV ------------
__global__ __launch_bounds__(128)
void attn_tc(const bf16* __restrict__ qkv, const float* __restrict__ bm,
             bf16* __restrict__ out)
{
    __shared__ bf16 qs [64][40];
    __shared__ bf16 ks_[56][40];
    __shared__ bf16 vt [32][72];

    int win  = blockIdx.x;
    int tid  = threadIdx.x;
    int wid  = tid >> 5, lane = tid & 31;
    int g    = lane >> 2, t = lane & 3;
    const float scale = 0.17677669529663689f;

    const bf16* base = qkv + (size_t)win * NWIN * (3 * CC);
    int r0 = wid * 16 + g, r1 = r0 + 8;
    bool v0ok = r0 < NWIN, v1ok = r1 < NWIN;

    for (int h = 0; h < NHEADS; h++) {
        for (int p = tid; p < 64 * HD; p += 128) {
            int n = p >> 5, d = p & 31;
            qs[n][d] = (n < NWIN) ? base[(size_t)n * (3 * CC) + h * HD + d] : (bf16)0.f;
        }
        for (int p = tid; p < 64 * HD; p += 128) {
            int n = p >> 5, d = p & 31;
            bf16 kv = (n < NWIN) ? base[(size_t)n * (3 * CC) + CC + h * HD + d] : (bf16)0.f;
            bf16 vv = (n < NWIN) ? base[(size_t)n * (3 * CC) + 2 * CC + h * HD + d] : (bf16)0.f;
            if (n < 56) ks_[n][d] = kv;
            vt[d][n] = vv;
        }
        __syncthreads();

        float sc[7][4];
        #pragma unroll
        for (int nt = 0; nt < 7; nt++)
            #pragma unroll
            for (int l = 0; l < 4; l++) sc[nt][l] = 0.f;

        #pragma unroll
        for (int ks = 0; ks < 2; ks++) {
            int kc = ks * 16 + 2 * t;
            uint32_t a0 = *(const uint32_t*)&qs[r0][kc];
            uint32_t a1 = *(const uint32_t*)&qs[r1][kc];
            uint32_t a2 = *(const uint32_t*)&qs[r0][kc + 8];
            uint32_t a3 = *(const uint32_t*)&qs[r1][kc + 8];
            #pragma unroll
            for (int nt = 0; nt < 7; nt++) {
                int nr = nt * 8 + g;
                uint32_t b0 = *(const uint32_t*)&ks_[nr][kc];
                uint32_t b1 = *(const uint32_t*)&ks_[nr][kc + 8];
                mma_bf16(sc[nt], a0, a1, a2, a3, b0, b1);
            }
        }

        const float* bmh = bm + ((size_t)((win & 255) * 3 + h)) * (49 * 56);
        #pragma unroll
        for (int nt = 0; nt < 7; nt++) {
            int cbase = nt * 8 + 2 * t;
            #pragma unroll
            for (int j = 0; j < 2; j++) {
                sc[nt][j]     = v0ok ? sc[nt][j]     * scale + bmh[r0 * 56 + cbase + j] : 0.f;
                sc[nt][2 + j] = v1ok ? sc[nt][2 + j] * scale + bmh[r1 * 56 + cbase + j] : 0.f;
            }
        }

        float mx0 = -1e30f, mx1 = -1e30f;
        #pragma unroll
        for (int nt = 0; nt < 7; nt++) {
            mx0 = fmaxf(mx0, fmaxf(sc[nt][0], sc[nt][1]));
            mx1 = fmaxf(mx1, fmaxf(sc[nt][2], sc[nt][3]));
        }
        #pragma unroll
        for (int o = 1; o <= 2; o <<= 1) {
            mx0 = fmaxf(mx0, __shfl_xor_sync(0xffffffffu, mx0, o));
            mx1 = fmaxf(mx1, __shfl_xor_sync(0xffffffffu, mx1, o));
        }
        float sum0 = 0.f, sum1 = 0.f;
        #pragma unroll
        for (int nt = 0; nt < 7; nt++) {
            sc[nt][0] = __expf(sc[nt][0] - mx0); sum0 += sc[nt][0];
            sc[nt][1] = __expf(sc[nt][1] - mx0); sum0 += sc[nt][1];
            sc[nt][2] = __expf(sc[nt][2] - mx1); sum1 += sc[nt][2];
            sc[nt][3] = __expf(sc[nt][3] - mx1); sum1 += sc[nt][3];
        }
        #pragma unroll
        for (int o = 1; o <= 2; o <<= 1) {
            sum0 += __shfl_xor_sync(0xffffffffu, sum0, o);
            sum1 += __shfl_xor_sync(0xffffffffu, sum1, o);
        }
        float inv0 = 1.0f / sum0, inv1 = 1.0f / sum1;
        #pragma unroll
        for (int nt = 0; nt < 7; nt++) {
            sc[nt][0] *= inv0; sc[nt][1] *= inv0;
            sc[nt][2] *= inv1; sc[nt][3] *= inv1;
        }

        float oc[4][4];
        #pragma unroll
        for (int nt = 0; nt < 4; nt++)
            #pragma unroll
            for (int l = 0; l < 4; l++) oc[nt][l] = 0.f;

        #pragma unroll
        for (int ks = 0; ks < 4; ks++) {
            uint32_t a0 = pack_bf16x2(sc[2 * ks][0], sc[2 * ks][1]);
            uint32_t a1 = pack_bf16x2(sc[2 * ks][2], sc[2 * ks][3]);
            uint32_t a2 = 0, a3 = 0;
            if (ks < 3) {
                a2 = pack_bf16x2(sc[2 * ks + 1][0], sc[2 * ks + 1][1]);
                a3 = pack_bf16x2(sc[2 * ks + 1][2], sc[2 * ks + 1][3]);
            }
            int kc = ks * 16 + 2 * t;
            #pragma unroll
            for (int nt = 0; nt < 4; nt++) {
                int nr = nt * 8 + g;
                uint32_t b0 = *(const uint32_t*)&vt[nr][kc];
                uint32_t b1 = *(const uint32_t*)&vt[nr][kc + 8];
                mma_bf16(oc[nt], a0, a1, a2, a3, b0, b1);
            }
        }

        #pragma unroll
        for (int nt = 0; nt < 4; nt++) {
            int d = nt * 8 + 2 * t;
            if (v0ok)
                *(uint32_t*)(out + ((size_t)win * NWIN + r0) * CC + h * HD + d) =
                    pack_bf16x2(oc[nt][0], oc[nt][1]);
            if (v1ok)
                *(uint32_t*)(out + ((size_t)win * NWIN + r1) * CC + h * HD + d) =
                    pack_bf16x2(oc[nt][2], oc[nt][3]);
        }
        __syncthreads();
    }
}

// ---------------- launch ----------------
extern "C" void kernel_launch(void* const* d_in, const int* in_sizes, int n_in,
                              void* d_out, int out_size)
{
    const float* x      = (const float*)d_in[0];
    const float* mask   = (const float*)d_in[1];
    const float* n1g    = (const float*)d_in[2];
    const float* n1b    = (const float*)d_in[3];
    const float* qkv_w  = (const float*)d_in[4];
    const float* qkv_b  = (const float*)d_in[5];
    const float* relb   = (const float*)d_in[6];
    const float* proj_w = (const float*)d_in[7];
    const float* proj_b = (const float*)d_in[8];
    const float* n2g    = (const float*)d_in[9];
    const float* n2b    = (const float*)d_in[10];
    const float* fc1_w  = (const float*)d_in[11];
    const float* fc1_b  = (const float*)d_in[12];
    const float* fc2_w  = (const float*)d_in[13];
    const float* fc2_b  = (const float*)d_in[14];
    float* out = (float*)d_out;

    bf16 *xw, *qkvb, *att, *y, *h1, *wb;
    float *x1, *bm;
    cudaGetSymbolAddress((void**)&xw,   g_xw);
    cudaGetSymbolAddress((void**)&qkvb, g_qkv);
    cudaGetSymbolAddress((void**)&att,  g_att);
    cudaGetSymbolAddress((void**)&x1,   g_x1);
    cudaGetSymbolAddress((void**)&y,    g_y);
    cudaGetSymbolAddress((void**)&h1,   g_h1);
    cudaGetSymbolAddress((void**)&wb,   g_wb);
    cudaGetSymbolAddress((void**)&bm,   g_bm);

    const int LN_BLOCKS = M_TOK / 8;
    const int GM = M_TOK / 128;         // 1568

    const int SM1    = (128 + 96) * SSTR * 2;       // 46592 B  (KTILES=1)
    const int SMPROJ = 128 * 96 * 4;                // 49152 B  (LN scratch)
    const int SM4    = 2 * (128 + 96) * SSTR * 2;   // 93184 B  (KTILES=4)

    cudaFuncSetAttribute((const void*)gemm_tc<1, 0, bf16>,
                         cudaFuncAttributeMaxDynamicSharedMemorySize, SM1);
    cudaFuncSetAttribute((const void*)gemm_tc<1, 2, float>,
                         cudaFuncAttributeMaxDynamicSharedMemorySize, SMPROJ);
    cudaFuncSetAttribute((const void*)gemm_tc<1, 1, bf16>,
                         cudaFuncAttributeMaxDynamicSharedMemorySize, SM1);
    cudaFuncSetAttribute((const void*)gemm_tc<4, 3, float>,
                         cudaFuncAttributeMaxDynamicSharedMemorySize, SM4);

    convert_w<<<(W_TOT + 255) / 256, 256>>>(qkv_w, proj_w, fc1_w, fc2_w, wb);
    build_bm<<<(BM_ELEMS + 255) / 256, 256>>>(relb, mask, bm);
    ln_kernel<<<LN_BLOCKS, 256>>>(x, n1g, n1b, xw);
    gemm_tc<1, 0, bf16><<<dim3(GM, 3), 384, SM1>>>(xw, wb + W_QKV, qkv_b, qkvb,
                                                   nullptr, 3 * CC, nullptr, nullptr, nullptr);
    attn_tc<<<BB * NW_IMG, 128>>>(qkvb, bm, att);
    gemm_tc<1, 2, float><<<dim3(GM, 1), 384, SMPROJ>>>(att, wb + W_PROJ, proj_b, x1,
                                                       x, CC, n2g, n2b, y);
    gemm_tc<1, 1, bf16><<<dim3(GM, 4), 384, SM1>>>(y, wb + W_FC1, fc1_b, h1,
                                                   nullptr, HID_D, nullptr, nullptr, nullptr);
    gemm_tc<4, 3, float><<<dim3(GM, 1), 384, SM4>>>(h1, wb + W_FC2, fc2_b, out,
                                                    x1, CC, nullptr, nullptr, nullptr);
}

// round 17
// speedup vs baseline: 1.7982x; 1.0502x over previous
#include <cuda_runtime.h>
#include <cuda_bf16.h>
#include <math.h>
#include <stdint.h>

// ---------------- problem constants ----------------
#define BB     16
#define HH     112
#define WWID   112
#define CC     96
#define NHEADS 3
#define HD     32
#define WS     7
#define NWIN   49
#define SHIFT  3
#define NW_IMG 256
#define M_TOK  200704
#define HID_D  384

typedef __nv_bfloat16 bf16;

#define W_QKV  0
#define W_PROJ 27648
#define W_FC1  36864
#define W_FC2  73728
#define W_TOT  110592

#define BM_ELEMS (256 * 3 * 49 * 56)
#define SSTR 104

// ---------------- scratch ----------------
__device__ bf16  g_xw [(size_t)M_TOK * CC];
__device__ bf16  g_qkv[(size_t)M_TOK * 3 * CC];
__device__ bf16  g_att[(size_t)M_TOK * CC];
__device__ float g_x1 [(size_t)M_TOK * CC];
__device__ bf16  g_y  [(size_t)M_TOK * CC];
__device__ bf16  g_h1 [(size_t)M_TOK * HID_D];
__device__ bf16  g_wb [W_TOT];
__device__ float g_bm [BM_ELEMS];

// ---------------- asm helpers ----------------
__device__ __forceinline__ void mma_bf16(float* c, uint32_t a0, uint32_t a1,
                                         uint32_t a2, uint32_t a3,
                                         uint32_t b0, uint32_t b1) {
    asm volatile(
        "mma.sync.aligned.m16n8k16.row.col.f32.bf16.bf16.f32 "
        "{%0,%1,%2,%3}, {%4,%5,%6,%7}, {%8,%9}, {%0,%1,%2,%3};"
        : "+f"(c[0]), "+f"(c[1]), "+f"(c[2]), "+f"(c[3])
        : "r"(a0), "r"(a1), "r"(a2), "r"(a3), "r"(b0), "r"(b1));
}

__device__ __forceinline__ void ldsm4(uint32_t& r0, uint32_t& r1,
                                      uint32_t& r2, uint32_t& r3, uint32_t addr) {
    asm volatile("ldmatrix.sync.aligned.m8n8.x4.shared.b16 {%0,%1,%2,%3}, [%4];"
                 : "=r"(r0), "=r"(r1), "=r"(r2), "=r"(r3) : "r"(addr));
}

__device__ __forceinline__ void cp16(uint32_t saddr, const void* g) {
    asm volatile("cp.async.ca.shared.global [%0], [%1], 16;" :: "r"(saddr), "l"(g));
}
__device__ __forceinline__ void cp_commit() { asm volatile("cp.async.commit_group;"); }
__device__ __forceinline__ void cp_wait0()  { asm volatile("cp.async.wait_group 0;"); }
__device__ __forceinline__ void cp_wait1()  { asm volatile("cp.async.wait_group 1;"); }

__device__ __forceinline__ uint32_t pack_bf16x2(float lo, float hi) {
    uint32_t r;
    asm("cvt.rn.bf16x2.f32 %0, %1, %2;" : "=r"(r) : "f"(hi), "f"(lo));
    return r;
}

// scatter: window-layout row m -> (B,L,C) base index (reverse shift)
__device__ __forceinline__ size_t scatter_base(int m) {
    int win = m / NWIN, nn = m % NWIN;
    int b  = win >> 8;
    int wi = win & 255;
    int wh = wi >> 4, ww = wi & 15;
    int ii = nn / WS, jj = nn % WS;
    int r = wh * WS + ii + SHIFT; if (r >= HH)   r -= HH;
    int c = ww * WS + jj + SHIFT; if (c >= WWID) c -= WWID;
    return ((size_t)b * (HH * WWID) + r * WWID + c) * CC;
}

// ---------------- setup kernels ----------------
__global__ void convert_w(const float* __restrict__ qkv_w, const float* __restrict__ proj_w,
                          const float* __restrict__ fc1_w, const float* __restrict__ fc2_w,
                          bf16* __restrict__ wb)
{
    int i = blockIdx.x * 256 + threadIdx.x;
    if (i >= W_TOT) return;
    float v;
    if      (i < W_PROJ) v = qkv_w[i - W_QKV];
    else if (i < W_FC1)  v = proj_w[i - W_PROJ];
    else if (i < W_FC2)  v = fc1_w[i - W_FC1];
    else                 v = fc2_w[i - W_FC2];
    wb[i] = __float2bfloat16(v);
}

__global__ void build_bm(const float* __restrict__ relb, const float* __restrict__ mask,
                         float* __restrict__ bm)
{
    int idx = blockIdx.x * 256 + threadIdx.x;
    if (idx >= BM_ELEMS) return;
    int c   = idx % 56;
    int tmp = idx / 56;
    int r   = tmp % 49;  tmp /= 49;
    int h   = tmp % 3;
    int wi  = tmp / 3;
    float v;
    if (c < 49) {
        int i1 = r / WS, j1 = r % WS, i2 = c / WS, j2 = c % WS;
        int ridx = (i1 - i2 + WS - 1) * (2 * WS - 1) + (j1 - j2 + WS - 1);
        v = relb[ridx * NHEADS + h] + mask[(size_t)wi * (NWIN * NWIN) + r * NWIN + c];
    } else {
        v = -1e9f;
    }
    bm[idx] = v;
}

// ---------------- LN1 (warp per token), gather + bf16 output ----------------
__global__ __launch_bounds__(256)
void ln_kernel(const float* __restrict__ x, const float* __restrict__ g,
               const float* __restrict__ beta, bf16* __restrict__ out)
{
    int t    = (blockIdx.x * blockDim.x + threadIdx.x) >> 5;
    int lane = threadIdx.x & 31;
    if (t >= M_TOK) return;

    int win = t / NWIN, n = t % NWIN;
    int b  = win >> 8;
    int wi = win & 255;
    int wh = wi >> 4, ww = wi & 15;
    int i = n / WS, j = n % WS;
    int r = wh * WS + i + SHIFT; if (r >= HH)   r -= HH;
    int c = ww * WS + j + SHIFT; if (c >= WWID) c -= WWID;
    const float* src = x + ((size_t)b * (HH * WWID) + r * WWID + c) * CC;

    float v0 = src[lane], v1 = src[lane + 32], v2 = src[lane + 64];
    float s = v0 + v1 + v2;
    #pragma unroll
    for (int o = 16; o; o >>= 1) s += __shfl_xor_sync(0xffffffffu, s, o);
    float mean = s * (1.0f / 96.0f);
    float d0 = v0 - mean, d1 = v1 - mean, d2 = v2 - mean;
    float q = d0 * d0 + d1 * d1 + d2 * d2;
    #pragma unroll
    for (int o = 16; o; o >>= 1) q += __shfl_xor_sync(0xffffffffu, q, o);
    float rstd = rsqrtf(q * (1.0f / 96.0f) + 1e-5f);

    bf16* dst = out + (size_t)t * CC;
    dst[lane]      = __float2bfloat16(d0 * rstd * g[lane]      + beta[lane]);
    dst[lane + 32] = __float2bfloat16(d1 * rstd * g[lane + 32] + beta[lane + 32]);
    dst[lane + 64] = __float2bfloat16(d2 * rstd * g[lane + 64] + beta[lane + 64]);
}

// ---------------- bf16 TC GEMM, K = KTILES*96 -------------------------------
template<int KTILES, int EPI, typename OUTT>
__global__ __launch_bounds__(384)
void gemm_tc(const bf16* __restrict__ A, const bf16* __restrict__ W,
             const float* __restrict__ bias, OUTT* __restrict__ out,
             const float* __restrict__ res, int N,
             const float* __restrict__ n2g, const float* __restrict__ n2b,
             bf16* __restrict__ yout)
{
    constexpr int K    = KTILES * 96;
    constexpr int NBUF = (KTILES > 1) ? 2 : 1;
    constexpr int ABUF = 128 * SSTR;

    extern __shared__ bf16 smem[];
    bf16*  As = smem;
    bf16*  Ws = smem + NBUF * ABUF;
    float* sx = (float*)smem;

    int tid  = threadIdx.x;
    int wid  = tid >> 5, lane = tid & 31;
    int g    = lane >> 2, t = lane & 3;
    int wm   = wid & 3, wn = wid >> 2;
    int m0   = blockIdx.x * 128, n0 = blockIdx.y * 96;

    uint32_t as_base = (uint32_t)__cvta_generic_to_shared(As);
    uint32_t ws_base = (uint32_t)__cvta_generic_to_shared(Ws);

    int lrow = lane & 7, lsel = lane >> 3;
    int ra = (lsel & 1) * 8 + lrow;
    int caoff = (lsel >> 1) * 8;

    float c[2][4][4];
    #pragma unroll
    for (int i = 0; i < 2; i++)
        #pragma unroll
        for (int j = 0; j < 4; j++)
            #pragma unroll
            for (int l = 0; l < 4; l++) c[i][j][l] = 0.f;

    auto stage = [&](int buf, int kt) {
        #pragma unroll
        for (int i = 0; i < 4; i++) {
            int idx = tid + i * 384;
            int row = idx / 12, ch = idx % 12;
            cp16(as_base + ((buf * 128 + row) * SSTR + ch * 8) * 2,
                 A + (size_t)(m0 + row) * K + kt * 96 + ch * 8);
        }
        #pragma unroll
        for (int i = 0; i < 3; i++) {
            int idx = tid + i * 384;
            int row = idx / 12, ch = idx % 12;
            cp16(ws_base + ((buf * 96 + row) * SSTR + ch * 8) * 2,
                 W + (size_t)(n0 + row) * K + kt * 96 + ch * 8);
        }
    };

    stage(0, 0);
    cp_commit();

    #pragma unroll
    for (int kt = 0; kt < KTILES; kt++) {
        int buf = kt & 1;
        if (KTILES > 1 && kt + 1 < KTILES) {
            stage((kt + 1) & 1, kt + 1);
            cp_commit();
            cp_wait1();
        } else {
            cp_wait0();
        }
        __syncthreads();

        #pragma unroll
        for (int kk = 0; kk < 6; kk++) {
            int kc = kk * 16 + caoff;
            uint32_t a[2][4];
            #pragma unroll
            for (int mt = 0; mt < 2; mt++) {
                int row = wm * 32 + mt * 16 + ra;
                ldsm4(a[mt][0], a[mt][1], a[mt][2], a[mt][3],
                      as_base + ((buf * 128 + row) * SSTR + kc) * 2);
            }
            uint32_t b[2][4];
            #pragma unroll
            for (int np = 0; np < 2; np++) {
                int row = wn * 32 + np * 16 + ra;
                ldsm4(b[np][0], b[np][1], b[np][2], b[np][3],
                      ws_base + ((buf * 96 + row) * SSTR + kc) * 2);
            }
            #pragma unroll
            for (int nt = 0; nt < 4; nt++) {
                uint32_t b0 = b[nt >> 1][nt & 1];
                uint32_t b1 = b[nt >> 1][(nt & 1) + 2];
                #pragma unroll
                for (int mt = 0; mt < 2; mt++)
                    mma_bf16(c[mt][nt], a[mt][0], a[mt][1], a[mt][2], a[mt][3], b0, b1);
            }
        }
        if (KTILES > 1 && kt + 1 < KTILES) __syncthreads();
    }

    if (EPI == 2) __syncthreads();

    #pragma unroll
    for (int mt = 0; mt < 2; mt++) {
        #pragma unroll
        for (int rh = 0; rh < 2; rh++) {
            int m = m0 + wm * 32 + mt * 16 + g + rh * 8;
            size_t rowbase;
            if (EPI == 2) rowbase = scatter_base(m);
            else          rowbase = (size_t)m * N;
            #pragma unroll
            for (int nt = 0; nt < 4; nt++) {
                int n = n0 + wn * 32 + nt * 8 + 2 * t;
                float v0 = c[mt][nt][rh * 2 + 0] + bias[n];
                float v1 = c[mt][nt][rh * 2 + 1] + bias[n + 1];
                if (EPI == 0) {
                    *(uint32_t*)((bf16*)out + rowbase + n) = pack_bf16x2(v0, v1);
                } else if (EPI == 1) {
                    float g0 = 0.5f * v0 * (1.0f + erff(v0 * 0.70710678118654752f));
                    float g1 = 0.5f * v1 * (1.0f + erff(v1 * 0.70710678118654752f));
                    *(uint32_t*)((bf16*)out + rowbase + n) = pack_bf16x2(g0, g1);
                } else if (EPI == 2) {
                    float2 rv = *(const float2*)(res + rowbase + n);
                    float x0 = rv.x + v0, x1v = rv.y + v1;
                    float2 ov; ov.x = x0; ov.y = x1v;
                    *(float2*)((float*)out + rowbase + n) = ov;
                    sx[(m - m0) * 96 + n]     = x0;
                    sx[(m - m0) * 96 + n + 1] = x1v;
                } else {
                    float2 rv = *(const float2*)(res + rowbase + n);
                    float2 ov; ov.x = rv.x + v0; ov.y = rv.y + v1;
                    *(float2*)((float*)out + rowbase + n) = ov;
                }
            }
        }
    }

    if (EPI == 2) {
        __syncthreads();
        for (int tok = wid; tok < 128; tok += 12) {
            float v0 = sx[tok * 96 + lane];
            float v1 = sx[tok * 96 + lane + 32];
            float v2 = sx[tok * 96 + lane + 64];
            float s = v0 + v1 + v2;
            #pragma unroll
            for (int o = 16; o; o >>= 1) s += __shfl_xor_sync(0xffffffffu, s, o);
            float mean = s * (1.0f / 96.0f);
            float d0 = v0 - mean, d1 = v1 - mean, d2 = v2 - mean;
            float q = d0 * d0 + d1 * d1 + d2 * d2;
            #pragma unroll
            for (int o = 16; o; o >>= 1) q += __shfl_xor_sync(0xffffffffu, q, o);
            float rstd = rsqrtf(q * (1.0f / 96.0f) + 1e-5f);
            size_t rb = scatter_base(m0 + tok);
            yout[rb + lane]      = __float2bfloat16(d0 * rstd * n2g[lane]      + n2b[lane]);
            yout[rb + lane + 32] = __float2bfloat16(d1 * rstd * n2g[lane + 32] + n2b[lane + 32]);
            yout[rb + lane + 64] = __float2bfloat16(d2 * rstd * n2g[lane + 64] + n2b[lane + 64]);
        }
    }
}

// ---------------- attention: vectorized staging, register softmax -----------
__global__ __launch_bounds__(128)
void attn_tc(const bf16* __restrict__ qkv, const float* __restrict__ bm,
             bf16* __restrict__ out)
{
    __shared__ bf16 qs [64][40];
    __shared__ bf16 ks_[56][40];
    __shared__ bf16 vt [32][72];

    int win  = blockIdx.x;
    int tid  = threadIdx.x;
    int wid  = tid >> 5, lane = tid & 31;
    int g    = lane >> 2, t = lane & 3;
    const float scale = 0.17677669529663689f;

    const bf16* base = qkv + (size_t)win * NWIN * (3 * CC);
    int r0 = wid * 16 + g, r1 = r0 + 8;
    bool v0ok = r0 < NWIN, v1ok = r1 < NWIN;

    for (int h = 0; h < NHEADS; h++) {
        // ---- vectorized staging: uint2 (4 bf16) chunks ----
        // Q: 64 rows x 8 chunks = 512 chunks
        for (int p = tid; p < 512; p += 128) {
            int n = p >> 3, c4 = (p & 7) << 2;
            uint2 qv = make_uint2(0u, 0u);
            if (n < NWIN)
                qv = *(const uint2*)(base + (size_t)n * (3 * CC) + h * HD + c4);
            *(uint2*)&qs[n][c4] = qv;
        }
        // K (rows<56) + V (transposed): 64 rows x 8 chunks
        for (int p = tid; p < 512; p += 128) {
            int n = p >> 3, c4 = (p & 7) << 2;
            uint2 kv = make_uint2(0u, 0u), vv = make_uint2(0u, 0u);
            if (n < NWIN) {
                kv = *(const uint2*)(base + (size_t)n * (3 * CC) + CC + h * HD + c4);
                vv = *(const uint2*)(base + (size_t)n * (3 * CC) + 2 * CC + h * HD + c4);
            }
            if (n < 56) *(uint2*)&ks_[n][c4] = kv;
            bf16 vb[4];
            *(uint2*)vb = vv;
            vt[c4 + 0][n] = vb[0];
            vt[c4 + 1][n] = vb[1];
            vt[c4 + 2][n] = vb[2];
            vt[c4 + 3][n] = vb[3];
        }
        __syncthreads();

        float sc[7][4];
        #pragma unroll
        for (int nt = 0; nt < 7; nt++)
            #pragma unroll
            for (int l = 0; l < 4; l++) sc[nt][l] = 0.f;

        #pragma unroll
        for (int ks = 0; ks < 2; ks++) {
            int kc = ks * 16 + 2 * t;
            uint32_t a0 = *(const uint32_t*)&qs[r0][kc];
            uint32_t a1 = *(const uint32_t*)&qs[r1][kc];
            uint32_t a2 = *(const uint32_t*)&qs[r0][kc + 8];
            uint32_t a3 = *(const uint32_t*)&qs[r1][kc + 8];
            #pragma unroll
            for (int nt = 0; nt < 7; nt++) {
                int nr = nt * 8 + g;
                uint32_t b0 = *(const uint32_t*)&ks_[nr][kc];
                uint32_t b1 = *(const uint32_t*)&ks_[nr][kc + 8];
                mma_bf16(sc[nt], a0, a1, a2, a3, b0, b1);
            }
        }

        const float* bmh = bm + ((size_t)((win & 255) * 3 + h)) * (49 * 56);
        #pragma unroll
        for (int nt = 0; nt < 7; nt++) {
            int cbase = nt * 8 + 2 * t;
            #pragma unroll
            for (int j = 0; j < 2; j++) {
                sc[nt][j]     = v0ok ? sc[nt][j]     * scale + bmh[r0 * 56 + cbase + j] : 0.f;
                sc[nt][2 + j] = v1ok ? sc[nt][2 + j] * scale + bmh[r1 * 56 + cbase + j] : 0.f;
            }
        }

        float mx0 = -1e30f, mx1 = -1e30f;
        #pragma unroll
        for (int nt = 0; nt < 7; nt++) {
            mx0 = fmaxf(mx0, fmaxf(sc[nt][0], sc[nt][1]));
            mx1 = fmaxf(mx1, fmaxf(sc[nt][2], sc[nt][3]));
        }
        #pragma unroll
        for (int o = 1; o <= 2; o <<= 1) {
            mx0 = fmaxf(mx0, __shfl_xor_sync(0xffffffffu, mx0, o));
            mx1 = fmaxf(mx1, __shfl_xor_sync(0xffffffffu, mx1, o));
        }
        float sum0 = 0.f, sum1 = 0.f;
        #pragma unroll
        for (int nt = 0; nt < 7; nt++) {
            sc[nt][0] = __expf(sc[nt][0] - mx0); sum0 += sc[nt][0];
            sc[nt][1] = __expf(sc[nt][1] - mx0); sum0 += sc[nt][1];
            sc[nt][2] = __expf(sc[nt][2] - mx1); sum1 += sc[nt][2];
            sc[nt][3] = __expf(sc[nt][3] - mx1); sum1 += sc[nt][3];
        }
        #pragma unroll
        for (int o = 1; o <= 2; o <<= 1) {
            sum0 += __shfl_xor_sync(0xffffffffu, sum0, o);
            sum1 += __shfl_xor_sync(0xffffffffu, sum1, o);
        }
        float inv0 = 1.0f / sum0, inv1 = 1.0f / sum1;
        #pragma unroll
        for (int nt = 0; nt < 7; nt++) {
            sc[nt][0] *= inv0; sc[nt][1] *= inv0;
            sc[nt][2] *= inv1; sc[nt][3] *= inv1;
        }

        float oc[4][4];
        #pragma unroll
        for (int nt = 0; nt < 4; nt++)
            #pragma unroll
            for (int l = 0; l < 4; l++) oc[nt][l] = 0.f;

        #pragma unroll
        for (int ks = 0; ks < 4; ks++) {
            uint32_t a0 = pack_bf16x2(sc[2 * ks][0], sc[2 * ks][1]);
            uint32_t a1 = pack_bf16x2(sc[2 * ks][2], sc[2 * ks][3]);
            uint32_t a2 = 0, a3 = 0;
            if (ks < 3) {
                a2 = pack_bf16x2(sc[2 * ks + 1][0], sc[2 * ks + 1][1]);
                a3 = pack_bf16x2(sc[2 * ks + 1][2], sc[2 * ks + 1][3]);
            }
            int kc = ks * 16 + 2 * t;
            #pragma unroll
            for (int nt = 0; nt < 4; nt++) {
                int nr = nt * 8 + g;
                uint32_t b0 = *(const uint32_t*)&vt[nr][kc];
                uint32_t b1 = *(const uint32_t*)&vt[nr][kc + 8];
                mma_bf16(oc[nt], a0, a1, a2, a3, b0, b1);
            }
        }

        #pragma unroll
        for (int nt = 0; nt < 4; nt++) {
            int d = nt * 8 + 2 * t;
            if (v0ok)
                *(uint32_t*)(out + ((size_t)win * NWIN + r0) * CC + h * HD + d) =
                    pack_bf16x2(oc[nt][0], oc[nt][1]);
            if (v1ok)
                *(uint32_t*)(out + ((size_t)win * NWIN + r1) * CC + h * HD + d) =
                    pack_bf16x2(oc[nt][2], oc[nt][3]);
        }
        __syncthreads();
    }
}

// ---------------- launch ----------------
extern "C" void kernel_launch(void* const* d_in, const int* in_sizes, int n_in,
                              void* d_out, int out_size)
{
    const float* x      = (const float*)d_in[0];
    const float* mask   = (const float*)d_in[1];
    const float* n1g    = (const float*)d_in[2];
    const float* n1b    = (const float*)d_in[3];
    const float* qkv_w  = (const float*)d_in[4];
    const float* qkv_b  = (const float*)d_in[5];
    const float* relb   = (const float*)d_in[6];
    const float* proj_w = (const float*)d_in[7];
    const float* proj_b = (const float*)d_in[8];
    const float* n2g    = (const float*)d_in[9];
    const float* n2b    = (const float*)d_in[10];
    const float* fc1_w  = (const float*)d_in[11];
    const float* fc1_b  = (const float*)d_in[12];
    const float* fc2_w  = (const float*)d_in[13];
    const float* fc2_b  = (const float*)d_in[14];
    float* out = (float*)d_out;

    bf16 *xw, *qkvb, *att, *y, *h1, *wb;
    float *x1, *bm;
    cudaGetSymbolAddress((void**)&xw,   g_xw);
    cudaGetSymbolAddress((void**)&qkvb, g_qkv);
    cudaGetSymbolAddress((void**)&att,  g_att);
    cudaGetSymbolAddress((void**)&x1,   g_x1);
    cudaGetSymbolAddress((void**)&y,    g_y);
    cudaGetSymbolAddress((void**)&h1,   g_h1);
    cudaGetSymbolAddress((void**)&wb,   g_wb);
    cudaGetSymbolAddress((void**)&bm,   g_bm);

    const int LN_BLOCKS = M_TOK / 8;
    const int GM = M_TOK / 128;         // 1568

    const int SM1    = (128 + 96) * SSTR * 2;       // 46592 B
    const int SMPROJ = 128 * 96 * 4;                // 49152 B
    const int SM4    = 2 * (128 + 96) * SSTR * 2;   // 93184 B

    cudaFuncSetAttribute((const void*)gemm_tc<1, 0, bf16>,
                         cudaFuncAttributeMaxDynamicSharedMemorySize, SM1);
    cudaFuncSetAttribute((const void*)gemm_tc<1, 2, float>,
                         cudaFuncAttributeMaxDynamicSharedMemorySize, SMPROJ);
    cudaFuncSetAttribute((const void*)gemm_tc<1, 1, bf16>,
                         cudaFuncAttributeMaxDynamicSharedMemorySize, SM1);
    cudaFuncSetAttribute((const void*)gemm_tc<4, 3, float>,
                         cudaFuncAttributeMaxDynamicSharedMemorySize, SM4);

    convert_w<<<(W_TOT + 255) / 256, 256>>>(qkv_w, proj_w, fc1_w, fc2_w, wb);
    build_bm<<<(BM_ELEMS + 255) / 256, 256>>>(relb, mask, bm);
    ln_kernel<<<LN_BLOCKS, 256>>>(x, n1g, n1b, xw);
    gemm_tc<1, 0, bf16><<<dim3(GM, 3), 384, SM1>>>(xw, wb + W_QKV, qkv_b, qkvb,
                                                   nullptr, 3 * CC, nullptr, nullptr, nullptr);
    attn_tc<<<BB * NW_IMG, 128>>>(qkvb, bm, att);
    gemm_tc<1, 2, float><<<dim3(GM, 1), 384, SMPROJ>>>(att, wb + W_PROJ, proj_b, x1,
                                                       x, CC, n2g, n2b, y);
    gemm_tc<1, 1, bf16><<<dim3(GM, 4), 384, SM1>>>(y, wb + W_FC1, fc1_b, h1,
                                                   nullptr, HID_D, nullptr, nullptr, nullptr);
    gemm_tc<4, 3, float><<<dim3(GM, 1), 384, SM4>>>(h1, wb + W_FC2, fc2_b, out,
                                                    x1, CC, nullptr, nullptr, nullptr);
}